// round 1
// baseline (speedup 1.0000x reference)
#include <cuda_runtime.h>
#include <math.h>

#define BSZ   1024
#define NB    30
#define KNN   10
#define HID   128
#define EMB   64
#define NROWS (BSZ*NB)

// ---------------- device scratch (no allocations allowed) ----------------
__device__ float g_cf[NB*EMB];        // tanh(class_feat) per node (batch-independent)
__device__ float g_Wcomb[192*256];    // [k][c]: c<128 -> Wc = W_m1[:192]-W_m1[192:], c>=128 -> Wd = W_m1[192:]
__device__ int   g_nbr[NROWS*KNN];    // within-batch neighbor node index
__device__ float g_A[NROWS*HID];      // f192 @ Wd
__device__ float g_C[NROWS*HID];      // f192 @ Wc + b_m1

// ---------------- kernel 0: tiny precompute ----------------
__global__ void k_setup(const float* __restrict__ emb_tab,
                        const float* __restrict__ W_emb,
                        const float* __restrict__ b_emb,
                        const float* __restrict__ W_m1)
{
    int tid = blockIdx.x * blockDim.x + threadIdx.x;
    int stride = gridDim.x * blockDim.x;
    // cf[n][e] = tanh( tanh(emb_tab[cat(n)]) @ W_emb + b_emb )
    for (int idx = tid; idx < NB*EMB; idx += stride) {
        int n = idx / EMB, e = idx - n*EMB;
        int cat = n / (NB/3);
        float s = b_emb[e];
        for (int k = 0; k < EMB; k++)
            s += tanhf(emb_tab[cat*EMB + k]) * W_emb[k*EMB + e];
        g_cf[idx] = tanhf(s);
    }
    // Wcomb
    for (int idx = tid; idx < 192*256; idx += stride) {
        int k = idx >> 8, c = idx & 255;
        float v;
        if (c < 128) v = W_m1[k*128 + c] - W_m1[(192+k)*128 + c];
        else         v = W_m1[(192+k)*128 + (c-128)];
        g_Wcomb[idx] = v;
    }
}

// ---------------- kernel 1: per-batch KNN (30 nodes, top-10 nearest) ----------------
__global__ void k_knn(const float* __restrict__ state_inp)
{
    __shared__ float px[NB], py[NB];
    int b = blockIdx.x, t = threadIdx.x;
    if (t < NB) { px[t] = state_inp[b*60 + 2*t]; py[t] = state_inp[b*60 + 2*t + 1]; }
    __syncthreads();
    if (t < NB) {
        float bd[KNN]; int bi[KNN];
        #pragma unroll
        for (int k = 0; k < KNN; k++) { bd[k] = 1e30f; bi[k] = 0; }
        float xi = px[t], yi = py[t];
        for (int j = 0; j < NB; j++) {
            if (j == t) continue;
            float dx = px[j] - xi, dy = py[j] - yi;
            float cd = dx*dx + dy*dy;
            int ci = j;
            #pragma unroll
            for (int k = 0; k < KNN; k++) {
                if (cd < bd[k]) {
                    float td = bd[k]; int ti = bi[k];
                    bd[k] = cd; bi[k] = ci; cd = td; ci = ti;
                }
            }
        }
        #pragma unroll
        for (int k = 0; k < KNN; k++) g_nbr[(b*NB + t)*KNN + k] = bi[k];
    }
}

// ---------------- kernel 2: feat MLP + A/C GEMM (32 rows per block) ----------------
__global__ __launch_bounds__(256) void k_feat(
    const float* __restrict__ state_inp, const float* __restrict__ tar,
    const float* __restrict__ W_in1, const float* __restrict__ b_in1,
    const float* __restrict__ W_in2, const float* __restrict__ b_in2,
    const float* __restrict__ b_m1)
{
    __shared__ float s_in4[32][4];
    __shared__ float s_t[128][34];   // transposed [k][row], pad 34 (8B aligned rows)
    __shared__ float s_f[192][34];   // [0:128)=tanh(h), [128:192)=cf
    const int tid = threadIdx.x;
    const int row0 = blockIdx.x * 32;

    if (tid < 128) {
        int r = tid >> 2, q = tid & 3;
        int row = row0 + r;
        int b = row / NB, n = row - b*NB;
        float v = (q < 2) ? state_inp[b*60 + 2*n + q] : tanhf(tar[row*2 + (q-2)]);
        s_in4[r][q] = v;
    }
    // cf part of feat (batch-independent, per node)
    for (int idx = tid; idx < 32*EMB; idx += 256) {
        int r = idx & 31, e = idx >> 5;
        int n = (row0 + r) % NB;
        s_f[128 + e][r] = g_cf[n*EMB + e];
    }
    __syncthreads();

    const int c  = tid & 127;
    const int rh = tid >> 7;
    const int rb = rh * 16;

    // stage 1: t = tanh(inp4 @ W_in1 + b_in1)
    {
        float w0 = W_in1[c], w1 = W_in1[128+c], w2 = W_in1[256+c], w3 = W_in1[384+c];
        float bb = b_in1[c];
        #pragma unroll
        for (int m = 0; m < 16; m++) {
            int r = rb + m;
            float4 in = *reinterpret_cast<const float4*>(&s_in4[r][0]);
            s_t[c][r] = tanhf(bb + w0*in.x + w1*in.y + w2*in.z + w3*in.w);
        }
    }
    __syncthreads();

    // stage 2: f = tanh(t @ W_in2 + b_in2)
    {
        float acc[16];
        #pragma unroll
        for (int m = 0; m < 16; m++) acc[m] = 0.f;
        #pragma unroll 4
        for (int k = 0; k < 128; k++) {
            float w = W_in2[k*128 + c];
            #pragma unroll
            for (int mm = 0; mm < 8; mm++) {
                float2 tv = *reinterpret_cast<const float2*>(&s_t[k][rb + 2*mm]);
                acc[2*mm]   += tv.x * w;
                acc[2*mm+1] += tv.y * w;
            }
        }
        float bb = b_in2[c];
        #pragma unroll
        for (int m = 0; m < 16; m++) s_f[c][rb + m] = tanhf(acc[m] + bb);
    }
    __syncthreads();

    // stage 3: [C | A] = f192 @ Wcomb (+b_m1 on C)
    {
        float acc[32];
        #pragma unroll
        for (int m = 0; m < 32; m++) acc[m] = 0.f;
        #pragma unroll 2
        for (int k = 0; k < 192; k++) {
            float w = g_Wcomb[k*256 + tid];
            #pragma unroll
            for (int mm = 0; mm < 16; mm++) {
                float2 fv = *reinterpret_cast<const float2*>(&s_f[k][2*mm]);
                acc[2*mm]   += fv.x * w;
                acc[2*mm+1] += fv.y * w;
            }
        }
        if (tid < 128) {
            float bb = b_m1[tid];
            #pragma unroll
            for (int m = 0; m < 32; m++) g_C[(row0+m)*128 + tid] = acc[m] + bb;
        } else {
            int ca = tid - 128;
            #pragma unroll
            for (int m = 0; m < 32; m++) g_A[(row0+m)*128 + ca] = acc[m];
        }
    }
}

// ---------------- kernel 3: edge msg GEMM + maxpool + actor head (16 rows/block) ----------------
__global__ __launch_bounds__(256) void k_msg(
    const float* __restrict__ tar,
    const float* __restrict__ W_m2, const float* __restrict__ b_m2,
    const float* __restrict__ W_a1, const float* __restrict__ b_a1,
    const float* __restrict__ W_a2, const float* __restrict__ b_a2,
    float* __restrict__ out)
{
    __shared__ float s_C[128][18];   // transposed [j][row]
    __shared__ float s_m[128][18];   // per-k tanh(C_i + A_j), transposed; reused for y later
    __shared__ float s_x[128][18];
    __shared__ int   s_nb[16*KNN];

    const int tid = threadIdx.x;
    const int row0 = blockIdx.x * 16;

    for (int idx = tid; idx < 16*128; idx += 256) {
        int r = idx >> 7, j = idx & 127;
        s_C[j][r] = g_C[(row0 + r)*128 + j];
    }
    if (tid < 16*KNN) {
        int r = tid / KNN;
        int b = (row0 + r) / NB;
        s_nb[tid] = b*NB + g_nbr[row0*KNN + tid];  // global row index of neighbor
    }
    __syncthreads();

    const int c  = tid & 127;
    const int rh = tid >> 7;
    const int rb = rh * 8;

    float vmax[8];
    #pragma unroll
    for (int m = 0; m < 8; m++) vmax[m] = -1e30f;

    for (int k = 0; k < KNN; k++) {
        // build m = tanh(C_i + A_j) for this k, transposed into shared
        for (int idx = tid; idx < 16*128; idx += 256) {
            int r = idx >> 7, j = idx & 127;
            float a = g_A[s_nb[r*KNN + k]*128 + j];
            s_m[j][r] = tanhf(s_C[j][r] + a);
        }
        __syncthreads();
        float acc[8];
        #pragma unroll
        for (int m = 0; m < 8; m++) acc[m] = 0.f;
        #pragma unroll 4
        for (int kk = 0; kk < 128; kk++) {
            float w = W_m2[kk*128 + c];
            #pragma unroll
            for (int mm = 0; mm < 4; mm++) {
                float2 mv = *reinterpret_cast<const float2*>(&s_m[kk][rb + 2*mm]);
                acc[2*mm]   += mv.x * w;
                acc[2*mm+1] += mv.y * w;
            }
        }
        #pragma unroll
        for (int m = 0; m < 8; m++) vmax[m] = fmaxf(vmax[m], acc[m]);
        __syncthreads();
    }

    // x = tanh(max + b_m2)
    {
        float bb = b_m2[c];
        #pragma unroll
        for (int m = 0; m < 8; m++) s_x[c][rb + m] = tanhf(vmax[m] + bb);
    }
    __syncthreads();

    // y = tanh(x @ W_a1 + b_a1)  (store into s_m, transposed)
    {
        float acc[8];
        #pragma unroll
        for (int m = 0; m < 8; m++) acc[m] = 0.f;
        #pragma unroll 4
        for (int kk = 0; kk < 128; kk++) {
            float w = W_a1[kk*128 + c];
            #pragma unroll
            for (int mm = 0; mm < 4; mm++) {
                float2 xv = *reinterpret_cast<const float2*>(&s_x[kk][rb + 2*mm]);
                acc[2*mm]   += xv.x * w;
                acc[2*mm+1] += xv.y * w;
            }
        }
        float bb = b_a1[c];
        #pragma unroll
        for (int m = 0; m < 8; m++) s_m[c][rb + m] = tanhf(acc[m] + bb);
    }
    __syncthreads();

    // final 128 -> 4 + squashing + output
    if (tid < 64) {
        int r = tid >> 2, o = tid & 3;
        float s = b_a2[o];
        #pragma unroll 4
        for (int kk = 0; kk < 128; kk++) s += s_m[kk][r] * W_a2[kk*4 + o];
        int row = row0 + r;
        int b = row / NB, n = row - b*NB;
        if (o < 2) {
            float tv = tar[row*2 + o];
            out[b*60 + 2*n + o] = 0.3f*tanhf(s) + 0.3f*tanhf(tv);
        } else {
            float t = tanhf(s);
            float ls = 3.5f*t - 1.5f;              // LSMIN + 0.5*(LSMAX-LSMIN)*(t+1)
            out[BSZ*60 + b*60 + 2*n + (o-2)] = expf(ls);
        }
    }
}

// ---------------- launch ----------------
extern "C" void kernel_launch(void* const* d_in, const int* in_sizes, int n_in,
                              void* d_out, int out_size)
{
    const float* state_inp = (const float*)d_in[0];
    const float* tar       = (const float*)d_in[1];
    const float* W_in1     = (const float*)d_in[2];
    const float* b_in1     = (const float*)d_in[3];
    const float* W_in2     = (const float*)d_in[4];
    const float* b_in2     = (const float*)d_in[5];
    const float* emb_tab   = (const float*)d_in[6];
    const float* W_emb     = (const float*)d_in[7];
    const float* b_emb     = (const float*)d_in[8];
    const float* W_m1      = (const float*)d_in[9];
    const float* b_m1      = (const float*)d_in[10];
    const float* W_m2      = (const float*)d_in[11];
    const float* b_m2      = (const float*)d_in[12];
    const float* W_a1      = (const float*)d_in[13];
    const float* b_a1      = (const float*)d_in[14];
    const float* W_a2      = (const float*)d_in[15];
    const float* b_a2      = (const float*)d_in[16];
    float* out = (float*)d_out;

    k_setup<<<64, 256>>>(emb_tab, W_emb, b_emb, W_m1);
    k_knn<<<BSZ, 32>>>(state_inp);
    k_feat<<<NROWS/32, 256>>>(state_inp, tar, W_in1, b_in1, W_in2, b_in2, b_m1);
    k_msg<<<NROWS/16, 256>>>(tar, W_m2, b_m2, W_a1, b_a1, W_a2, b_a2, out);
}

// round 2
// speedup vs baseline: 1.0747x; 1.0747x over previous
#include <cuda_runtime.h>
#include <math.h>

#define BSZ   1024
#define NB    30
#define KNN   10
#define HID   128
#define EMB   64
#define NROWS (BSZ*NB)
#define P     34          // shared pitch (floats): broadcast-friendly, 8B aligned rows

__device__ __forceinline__ float tanha(float x) {
    float y; asm("tanh.approx.f32 %0, %1;" : "=f"(y) : "f"(x)); return y;
}

// ---------------- device scratch ----------------
__device__ float g_cf[NB*EMB];
__device__ float g_Wcomb[192*256];    // [k][c]: c<128 -> Wc=W_m1[:192]-W_m1[192:], c>=128 -> Wd=W_m1[192:]
__device__ int   g_nbr[NROWS*KNN];
__device__ float g_A[NROWS*HID];
__device__ float g_C[NROWS*HID];

// ---------------- kernel 0: tiny precompute ----------------
__global__ void k_setup(const float* __restrict__ emb_tab,
                        const float* __restrict__ W_emb,
                        const float* __restrict__ b_emb,
                        const float* __restrict__ W_m1)
{
    int tid = blockIdx.x * blockDim.x + threadIdx.x;
    int stride = gridDim.x * blockDim.x;
    for (int idx = tid; idx < NB*EMB; idx += stride) {
        int n = idx / EMB, e = idx - n*EMB;
        int cat = n / (NB/3);
        float s = b_emb[e];
        for (int k = 0; k < EMB; k++)
            s += tanhf(emb_tab[cat*EMB + k]) * W_emb[k*EMB + e];
        g_cf[idx] = tanhf(s);
    }
    for (int idx = tid; idx < 192*256; idx += stride) {
        int k = idx >> 8, c = idx & 255;
        float v;
        if (c < 128) v = W_m1[k*128 + c] - W_m1[(192+k)*128 + c];
        else         v = W_m1[(192+k)*128 + (c-128)];
        g_Wcomb[idx] = v;
    }
}

// ---------------- kernel 1: per-batch KNN ----------------
__global__ void k_knn(const float* __restrict__ state_inp)
{
    __shared__ float px[NB], py[NB];
    int b = blockIdx.x, t = threadIdx.x;
    if (t < NB) { px[t] = state_inp[b*60 + 2*t]; py[t] = state_inp[b*60 + 2*t + 1]; }
    __syncthreads();
    if (t < NB) {
        float bd[KNN]; int bi[KNN];
        #pragma unroll
        for (int k = 0; k < KNN; k++) { bd[k] = 1e30f; bi[k] = 0; }
        float xi = px[t], yi = py[t];
        for (int j = 0; j < NB; j++) {
            if (j == t) continue;
            float dx = px[j] - xi, dy = py[j] - yi;
            float cd = dx*dx + dy*dy;
            int ci = j;
            #pragma unroll
            for (int k = 0; k < KNN; k++) {
                if (cd < bd[k]) {
                    float td = bd[k]; int ti = bi[k];
                    bd[k] = cd; bi[k] = ci; cd = td; ci = ti;
                }
            }
        }
        #pragma unroll
        for (int k = 0; k < KNN; k++) g_nbr[(b*NB + t)*KNN + k] = bi[k];
    }
}

// ---------------- kernel 2: feat MLP + A/C GEMM (32 rows/block) ----------------
__global__ __launch_bounds__(256, 2) void k_feat(
    const float* __restrict__ state_inp, const float* __restrict__ tar,
    const float* __restrict__ W_in1, const float* __restrict__ b_in1,
    const float* __restrict__ W_in2, const float* __restrict__ b_in2,
    const float* __restrict__ b_m1)
{
    __shared__ float s_in4[32][4];
    __shared__ float s_t[128][P];
    __shared__ float s_f[192][P];
    const int tid = threadIdx.x;
    const int row0 = blockIdx.x * 32;

    if (tid < 128) {
        int r = tid >> 2, q = tid & 3;
        int row = row0 + r;
        int b = row / NB, n = row - b*NB;
        float v = (q < 2) ? state_inp[b*60 + 2*n + q] : tanha(tar[row*2 + (q-2)]);
        s_in4[r][q] = v;
    }
    for (int idx = tid; idx < 32*EMB; idx += 256) {
        int r = idx & 31, e = idx >> 5;
        int n = (row0 + r) % NB;
        s_f[128 + e][r] = g_cf[n*EMB + e];
    }
    __syncthreads();

    // stage 1: t = tanh(inp4 @ W_in1 + b_in1)
    {
        const int c  = tid & 127;
        const int rh = tid >> 7;
        float w0 = W_in1[c], w1 = W_in1[128+c], w2 = W_in1[256+c], w3 = W_in1[384+c];
        float bb = b_in1[c];
        #pragma unroll
        for (int m = 0; m < 16; m++) {
            int r = rh*16 + m;
            float4 in = *reinterpret_cast<const float4*>(&s_in4[r][0]);
            s_t[c][r] = tanha(bb + w0*in.x + w1*in.y + w2*in.z + w3*in.w);
        }
    }
    __syncthreads();

    const int g  = tid >> 6;      // row group 0..3 -> rows 8g..8g+7
    const int rb = g*8;

    // stage 2: f = tanh(t @ W_in2 + b_in2), 8 rows x 2 cols per thread
    {
        const int c2 = tid & 63;
        float acc[8][2];
        #pragma unroll
        for (int m = 0; m < 8; m++) { acc[m][0] = 0.f; acc[m][1] = 0.f; }
        #pragma unroll 4
        for (int k = 0; k < 128; k++) {
            float2 w = *reinterpret_cast<const float2*>(&W_in2[k*128 + 2*c2]);
            #pragma unroll
            for (int q = 0; q < 4; q++) {
                float2 tv = *reinterpret_cast<const float2*>(&s_t[k][rb + 2*q]);
                acc[2*q  ][0] += tv.x*w.x;  acc[2*q  ][1] += tv.x*w.y;
                acc[2*q+1][0] += tv.y*w.x;  acc[2*q+1][1] += tv.y*w.y;
            }
        }
        float2 bb = *reinterpret_cast<const float2*>(&b_in2[2*c2]);
        #pragma unroll
        for (int m = 0; m < 8; m++) {
            s_f[2*c2  ][rb + m] = tanha(acc[m][0] + bb.x);
            s_f[2*c2+1][rb + m] = tanha(acc[m][1] + bb.y);
        }
    }
    __syncthreads();

    // stage 3: [C|A] = f192 @ Wcomb, 8 rows x 4 cols per thread
    {
        const int c4 = tid & 63;            // cols 4c4..4c4+3 of 256
        float acc[8][4];
        #pragma unroll
        for (int m = 0; m < 8; m++)
            #pragma unroll
            for (int n = 0; n < 4; n++) acc[m][n] = 0.f;
        #pragma unroll 2
        for (int k = 0; k < 192; k++) {
            float4 w = *reinterpret_cast<const float4*>(&g_Wcomb[k*256 + 4*c4]);
            #pragma unroll
            for (int q = 0; q < 4; q++) {
                float2 fv = *reinterpret_cast<const float2*>(&s_f[k][rb + 2*q]);
                acc[2*q  ][0] += fv.x*w.x; acc[2*q  ][1] += fv.x*w.y;
                acc[2*q  ][2] += fv.x*w.z; acc[2*q  ][3] += fv.x*w.w;
                acc[2*q+1][0] += fv.y*w.x; acc[2*q+1][1] += fv.y*w.y;
                acc[2*q+1][2] += fv.y*w.z; acc[2*q+1][3] += fv.y*w.w;
            }
        }
        if (c4 < 32) {
            float4 bb = *reinterpret_cast<const float4*>(&b_m1[4*c4]);
            #pragma unroll
            for (int m = 0; m < 8; m++) {
                float4 v = make_float4(acc[m][0]+bb.x, acc[m][1]+bb.y, acc[m][2]+bb.z, acc[m][3]+bb.w);
                *reinterpret_cast<float4*>(&g_C[(row0+rb+m)*128 + 4*c4]) = v;
            }
        } else {
            int ca = 4*c4 - 128;
            #pragma unroll
            for (int m = 0; m < 8; m++) {
                float4 v = make_float4(acc[m][0], acc[m][1], acc[m][2], acc[m][3]);
                *reinterpret_cast<float4*>(&g_A[(row0+rb+m)*128 + ca]) = v;
            }
        }
    }
}

// ---------------- kernel 3: edge msg + maxpool + actor head (32 rows/block) ----------------
__global__ __launch_bounds__(256, 3) void k_msg(
    const float* __restrict__ tar,
    const float* __restrict__ W_m2, const float* __restrict__ b_m2,
    const float* __restrict__ W_a1, const float* __restrict__ b_a1,
    const float* __restrict__ W_a2, const float* __restrict__ b_a2,
    float* __restrict__ out)
{
    __shared__ float s_m[128][P];     // tanh(C_i + A_j) transposed [j][row]; later reused for y
    __shared__ float s_x[128][P];
    __shared__ int   s_nb[32*KNN];

    const int tid = threadIdx.x;
    const int row0 = blockIdx.x * 32;

    for (int idx = tid; idx < 32*KNN; idx += 256) {
        int r = idx / KNN;
        int b = (row0 + r) / NB;
        s_nb[idx] = b*NB + g_nbr[row0*KNN + idx];
    }
    __syncthreads();

    const int c2 = tid & 63;          // cols 2c2, 2c2+1
    const int g  = tid >> 6;          // row group 0..3
    const int rb = g*8;

    float vmax[8][2];
    #pragma unroll
    for (int m = 0; m < 8; m++) { vmax[m][0] = -1e30f; vmax[m][1] = -1e30f; }

    for (int k = 0; k < KNN; k++) {
        // build m = tanh(C_i + A_j), transposed [j][r]
        #pragma unroll
        for (int it = 0; it < 16; it++) {
            int idx = tid + 256*it;
            int r = idx >> 7, j = idx & 127;
            int nrow = s_nb[r*KNN + k];
            float a = g_A[nrow*128 + j];
            float c = g_C[(row0+r)*128 + j];
            s_m[j][r] = tanha(c + a);
        }
        __syncthreads();

        float acc[8][2];
        #pragma unroll
        for (int m = 0; m < 8; m++) { acc[m][0] = 0.f; acc[m][1] = 0.f; }
        #pragma unroll 4
        for (int kk = 0; kk < 128; kk++) {
            float2 w = *reinterpret_cast<const float2*>(&W_m2[kk*128 + 2*c2]);
            #pragma unroll
            for (int q = 0; q < 4; q++) {
                float2 mv = *reinterpret_cast<const float2*>(&s_m[kk][rb + 2*q]);
                acc[2*q  ][0] += mv.x*w.x;  acc[2*q  ][1] += mv.x*w.y;
                acc[2*q+1][0] += mv.y*w.x;  acc[2*q+1][1] += mv.y*w.y;
            }
        }
        #pragma unroll
        for (int m = 0; m < 8; m++) {
            vmax[m][0] = fmaxf(vmax[m][0], acc[m][0]);
            vmax[m][1] = fmaxf(vmax[m][1], acc[m][1]);
        }
        __syncthreads();
    }

    // x = tanh(max + b_m2), transposed into s_x
    {
        float2 bb = *reinterpret_cast<const float2*>(&b_m2[2*c2]);
        #pragma unroll
        for (int m = 0; m < 8; m++) {
            s_x[2*c2  ][rb + m] = tanha(vmax[m][0] + bb.x);
            s_x[2*c2+1][rb + m] = tanha(vmax[m][1] + bb.y);
        }
    }
    __syncthreads();

    // y = tanh(x @ W_a1 + b_a1) into s_m (reuse)
    {
        float acc[8][2];
        #pragma unroll
        for (int m = 0; m < 8; m++) { acc[m][0] = 0.f; acc[m][1] = 0.f; }
        #pragma unroll 4
        for (int kk = 0; kk < 128; kk++) {
            float2 w = *reinterpret_cast<const float2*>(&W_a1[kk*128 + 2*c2]);
            #pragma unroll
            for (int q = 0; q < 4; q++) {
                float2 xv = *reinterpret_cast<const float2*>(&s_x[kk][rb + 2*q]);
                acc[2*q  ][0] += xv.x*w.x;  acc[2*q  ][1] += xv.x*w.y;
                acc[2*q+1][0] += xv.y*w.x;  acc[2*q+1][1] += xv.y*w.y;
            }
        }
        float2 bb = *reinterpret_cast<const float2*>(&b_a1[2*c2]);
        #pragma unroll
        for (int m = 0; m < 8; m++) {
            s_m[2*c2  ][rb + m] = tanha(acc[m][0] + bb.x);
            s_m[2*c2+1][rb + m] = tanha(acc[m][1] + bb.y);
        }
    }
    __syncthreads();

    // final 128 -> 4 + exact squashing + output
    if (tid < 128) {
        int r = tid >> 2, o = tid & 3;
        float s = b_a2[o];
        #pragma unroll 4
        for (int kk = 0; kk < 128; kk++) s += s_m[kk][r] * W_a2[kk*4 + o];
        int row = row0 + r;
        int b = row / NB, n = row - b*NB;
        if (o < 2) {
            float tv = tar[row*2 + o];
            out[b*60 + 2*n + o] = 0.3f*tanhf(s) + 0.3f*tanhf(tv);
        } else {
            float t = tanhf(s);
            float ls = 3.5f*t - 1.5f;
            out[BSZ*60 + b*60 + 2*n + (o-2)] = expf(ls);
        }
    }
}

// ---------------- launch ----------------
extern "C" void kernel_launch(void* const* d_in, const int* in_sizes, int n_in,
                              void* d_out, int out_size)
{
    const float* state_inp = (const float*)d_in[0];
    const float* tar       = (const float*)d_in[1];
    const float* W_in1     = (const float*)d_in[2];
    const float* b_in1     = (const float*)d_in[3];
    const float* W_in2     = (const float*)d_in[4];
    const float* b_in2     = (const float*)d_in[5];
    const float* emb_tab   = (const float*)d_in[6];
    const float* W_emb     = (const float*)d_in[7];
    const float* b_emb     = (const float*)d_in[8];
    const float* W_m1      = (const float*)d_in[9];
    const float* b_m1      = (const float*)d_in[10];
    const float* W_m2      = (const float*)d_in[11];
    const float* b_m2      = (const float*)d_in[12];
    const float* W_a1      = (const float*)d_in[13];
    const float* b_a1      = (const float*)d_in[14];
    const float* W_a2      = (const float*)d_in[15];
    const float* b_a2      = (const float*)d_in[16];
    float* out = (float*)d_out;

    k_setup<<<64, 256>>>(emb_tab, W_emb, b_emb, W_m1);
    k_knn<<<BSZ, 32>>>(state_inp);
    k_feat<<<NROWS/32, 256>>>(state_inp, tar, W_in1, b_in1, W_in2, b_in2, b_m1);
    k_msg<<<NROWS/32, 256>>>(tar, W_m2, b_m2, W_a1, b_a1, W_a2, b_a2, out);
}

// round 4
// speedup vs baseline: 1.1751x; 1.0934x over previous
#include <cuda_runtime.h>
#include <math.h>

#define BSZ   1024
#define NB    30
#define KNN   10
#define HID   128
#define EMB   64
#define NROWS (BSZ*NB)
#define P     34          // k_feat shared pitch
#define PM    66          // k_msg shared pitch (even -> 8B-aligned float2 rows)
#define RMSG  64          // rows per k_msg block

typedef unsigned long long u64;

__device__ __forceinline__ float tanha(float x) {
    float y; asm("tanh.approx.f32 %0, %1;" : "=f"(y) : "f"(x)); return y;
}
__device__ __forceinline__ u64 pk(float x) {            // (x,x) packed
    u64 d; asm("mov.b64 %0,{%1,%1};" : "=l"(d) : "f"(x)); return d;
}
__device__ __forceinline__ u64 fma2(u64 a, u64 b, u64 c) {
    u64 d; asm("fma.rn.f32x2 %0,%1,%2,%3;" : "=l"(d) : "l"(a), "l"(b), "l"(c)); return d;
}
__device__ __forceinline__ float2 up(u64 a) {
    float2 r; asm("mov.b64 {%0,%1},%2;" : "=f"(r.x), "=f"(r.y) : "l"(a)); return r;
}

// ---------------- device scratch ----------------
__device__ float g_cf[NB*EMB];
__device__ float g_Wcomb[192*256];
__device__ int   g_nbr[NROWS*KNN];
__device__ float g_A[NROWS*HID];
__device__ float g_C[NROWS*HID];

// ---------------- kernel 0: tiny precompute ----------------
__global__ void k_setup(const float* __restrict__ emb_tab,
                        const float* __restrict__ W_emb,
                        const float* __restrict__ b_emb,
                        const float* __restrict__ W_m1)
{
    int tid = blockIdx.x * blockDim.x + threadIdx.x;
    int stride = gridDim.x * blockDim.x;
    for (int idx = tid; idx < NB*EMB; idx += stride) {
        int n = idx / EMB, e = idx - n*EMB;
        int cat = n / (NB/3);
        float s = b_emb[e];
        for (int k = 0; k < EMB; k++)
            s += tanhf(emb_tab[cat*EMB + k]) * W_emb[k*EMB + e];
        g_cf[idx] = tanhf(s);
    }
    for (int idx = tid; idx < 192*256; idx += stride) {
        int k = idx >> 8, c = idx & 255;
        float v;
        if (c < 128) v = W_m1[k*128 + c] - W_m1[(192+k)*128 + c];
        else         v = W_m1[(192+k)*128 + (c-128)];
        g_Wcomb[idx] = v;
    }
}

// ---------------- kernel 1: per-batch KNN ----------------
__global__ void k_knn(const float* __restrict__ state_inp)
{
    __shared__ float px[NB], py[NB];
    int b = blockIdx.x, t = threadIdx.x;
    if (t < NB) { px[t] = state_inp[b*60 + 2*t]; py[t] = state_inp[b*60 + 2*t + 1]; }
    __syncthreads();
    if (t < NB) {
        float bd[KNN]; int bi[KNN];
        #pragma unroll
        for (int k = 0; k < KNN; k++) { bd[k] = 1e30f; bi[k] = 0; }
        float xi = px[t], yi = py[t];
        for (int j = 0; j < NB; j++) {
            if (j == t) continue;
            float dx = px[j] - xi, dy = py[j] - yi;
            float cd = dx*dx + dy*dy;
            int ci = j;
            #pragma unroll
            for (int k = 0; k < KNN; k++) {
                if (cd < bd[k]) {
                    float td = bd[k]; int ti = bi[k];
                    bd[k] = cd; bi[k] = ci; cd = td; ci = ti;
                }
            }
        }
        #pragma unroll
        for (int k = 0; k < KNN; k++) g_nbr[(b*NB + t)*KNN + k] = bi[k];
    }
}

// ---------------- kernel 2: feat MLP + A/C GEMM (32 rows/block) ----------------
__global__ __launch_bounds__(256, 2) void k_feat(
    const float* __restrict__ state_inp, const float* __restrict__ tar,
    const float* __restrict__ W_in1, const float* __restrict__ b_in1,
    const float* __restrict__ W_in2, const float* __restrict__ b_in2,
    const float* __restrict__ b_m1)
{
    __shared__ float s_in4[32][4];
    __shared__ float s_t[128][P];
    __shared__ float s_f[192][P];
    const int tid = threadIdx.x;
    const int row0 = blockIdx.x * 32;

    if (tid < 128) {
        int r = tid >> 2, q = tid & 3;
        int row = row0 + r;
        int b = row / NB, n = row - b*NB;
        float v = (q < 2) ? state_inp[b*60 + 2*n + q] : tanha(tar[row*2 + (q-2)]);
        s_in4[r][q] = v;
    }
    for (int idx = tid; idx < 32*EMB; idx += 256) {
        int r = idx & 31, e = idx >> 5;
        int n = (row0 + r) % NB;
        s_f[128 + e][r] = g_cf[n*EMB + e];
    }
    __syncthreads();

    // stage 1
    {
        const int c  = tid & 127;
        const int rh = tid >> 7;
        float w0 = W_in1[c], w1 = W_in1[128+c], w2 = W_in1[256+c], w3 = W_in1[384+c];
        float bb = b_in1[c];
        #pragma unroll
        for (int m = 0; m < 16; m++) {
            int r = rh*16 + m;
            float4 in = *reinterpret_cast<const float4*>(&s_in4[r][0]);
            s_t[c][r] = tanha(bb + w0*in.x + w1*in.y + w2*in.z + w3*in.w);
        }
    }
    __syncthreads();

    const int g  = tid >> 6;
    const int rb = g*8;

    // stage 2 (f32x2): 8 rows x 2 cols
    {
        const int c2 = tid & 63;
        u64 acc[4][2];
        #pragma unroll
        for (int q = 0; q < 4; q++) { acc[q][0] = 0ull; acc[q][1] = 0ull; }
        #pragma unroll 4
        for (int k = 0; k < 128; k++) {
            float2 w = *reinterpret_cast<const float2*>(&W_in2[k*128 + 2*c2]);
            u64 w0 = pk(w.x), w1 = pk(w.y);
            #pragma unroll
            for (int q = 0; q < 4; q++) {
                u64 tv = *reinterpret_cast<const u64*>(&s_t[k][rb + 2*q]);
                acc[q][0] = fma2(tv, w0, acc[q][0]);
                acc[q][1] = fma2(tv, w1, acc[q][1]);
            }
        }
        float2 bb = *reinterpret_cast<const float2*>(&b_in2[2*c2]);
        #pragma unroll
        for (int q = 0; q < 4; q++) {
            float2 a0 = up(acc[q][0]), a1 = up(acc[q][1]);
            s_f[2*c2  ][rb + 2*q]   = tanha(a0.x + bb.x);
            s_f[2*c2  ][rb + 2*q+1] = tanha(a0.y + bb.x);
            s_f[2*c2+1][rb + 2*q]   = tanha(a1.x + bb.y);
            s_f[2*c2+1][rb + 2*q+1] = tanha(a1.y + bb.y);
        }
    }
    __syncthreads();

    // stage 3 (f32x2): [C|A] = f192 @ Wcomb, 8 rows x 4 cols
    {
        const int c4 = tid & 63;
        u64 acc[4][4];
        #pragma unroll
        for (int q = 0; q < 4; q++)
            #pragma unroll
            for (int n = 0; n < 4; n++) acc[q][n] = 0ull;
        #pragma unroll 2
        for (int k = 0; k < 192; k++) {
            float4 w = *reinterpret_cast<const float4*>(&g_Wcomb[k*256 + 4*c4]);
            u64 w0 = pk(w.x), w1 = pk(w.y), w2 = pk(w.z), w3 = pk(w.w);
            #pragma unroll
            for (int q = 0; q < 4; q++) {
                u64 fv = *reinterpret_cast<const u64*>(&s_f[k][rb + 2*q]);
                acc[q][0] = fma2(fv, w0, acc[q][0]);
                acc[q][1] = fma2(fv, w1, acc[q][1]);
                acc[q][2] = fma2(fv, w2, acc[q][2]);
                acc[q][3] = fma2(fv, w3, acc[q][3]);
            }
        }
        if (c4 < 32) {
            float4 bb = *reinterpret_cast<const float4*>(&b_m1[4*c4]);
            #pragma unroll
            for (int q = 0; q < 4; q++) {
                float2 a0 = up(acc[q][0]), a1 = up(acc[q][1]), a2 = up(acc[q][2]), a3 = up(acc[q][3]);
                *reinterpret_cast<float4*>(&g_C[(row0+rb+2*q  )*128 + 4*c4]) =
                    make_float4(a0.x+bb.x, a1.x+bb.y, a2.x+bb.z, a3.x+bb.w);
                *reinterpret_cast<float4*>(&g_C[(row0+rb+2*q+1)*128 + 4*c4]) =
                    make_float4(a0.y+bb.x, a1.y+bb.y, a2.y+bb.z, a3.y+bb.w);
            }
        } else {
            int ca = 4*c4 - 128;
            #pragma unroll
            for (int q = 0; q < 4; q++) {
                float2 a0 = up(acc[q][0]), a1 = up(acc[q][1]), a2 = up(acc[q][2]), a3 = up(acc[q][3]);
                *reinterpret_cast<float4*>(&g_A[(row0+rb+2*q  )*128 + ca]) =
                    make_float4(a0.x, a1.x, a2.x, a3.x);
                *reinterpret_cast<float4*>(&g_A[(row0+rb+2*q+1)*128 + ca]) =
                    make_float4(a0.y, a1.y, a2.y, a3.y);
            }
        }
    }
}

// ---------------- kernel 3: edge msg + maxpool + actor head (64 rows/block, dynamic smem) ----------------
#define SM_M   0                    // float s_m[128][PM]
#define SM_X   (128*PM)             // float s_x[128][PM]
#define SM_NB  (2*128*PM)           // int   s_nb[RMSG*KNN]
#define SMEM_MSG_BYTES ((2*128*PM + RMSG*KNN) * 4)

__global__ __launch_bounds__(256, 2) void k_msg(
    const float* __restrict__ tar,
    const float* __restrict__ W_m2, const float* __restrict__ b_m2,
    const float* __restrict__ W_a1, const float* __restrict__ b_a1,
    const float* __restrict__ W_a2, const float* __restrict__ b_a2,
    float* __restrict__ out)
{
    extern __shared__ float smem[];
    float* s_m = smem + SM_M;       // [j*PM + r]
    float* s_x = smem + SM_X;
    int*   s_nb = (int*)(smem + SM_NB);

    const int tid  = threadIdx.x;
    const int row0 = blockIdx.x * RMSG;

    for (int idx = tid; idx < RMSG*KNN; idx += 256) {
        int r = idx / KNN;
        int b = (row0 + r) / NB;
        s_nb[idx] = b*NB + g_nbr[row0*KNN + idx];
    }
    __syncthreads();

    const int c4 = (tid & 31) * 4;   // cols c4..c4+3
    const int g  = tid >> 5;         // 8 row groups
    const int rb = g * 8;            // rows rb..rb+7

    float vmax[8][4];
    #pragma unroll
    for (int m = 0; m < 8; m++)
        #pragma unroll
        for (int n = 0; n < 4; n++) vmax[m][n] = -1e30f;

    for (int k = 0; k < KNN; k++) {
        // build m = tanh(C_i + A_j), transposed [j][r]
        #pragma unroll
        for (int it = 0; it < 32; it++) {
            int idx = tid + 256*it;
            int r = idx >> 7, j = idx & 127;
            float a = g_A[s_nb[r*KNN + k]*128 + j];
            float c = g_C[(row0 + r)*128 + j];
            s_m[j*PM + r] = tanha(c + a);
        }
        __syncthreads();

        u64 acc[4][4];
        #pragma unroll
        for (int q = 0; q < 4; q++)
            #pragma unroll
            for (int n = 0; n < 4; n++) acc[q][n] = 0ull;
        #pragma unroll 4
        for (int kk = 0; kk < 128; kk++) {
            float4 w = *reinterpret_cast<const float4*>(&W_m2[kk*128 + c4]);
            u64 w0 = pk(w.x), w1 = pk(w.y), w2 = pk(w.z), w3 = pk(w.w);
            #pragma unroll
            for (int q = 0; q < 4; q++) {
                u64 rp = *reinterpret_cast<const u64*>(&s_m[kk*PM + rb + 2*q]);
                acc[q][0] = fma2(rp, w0, acc[q][0]);
                acc[q][1] = fma2(rp, w1, acc[q][1]);
                acc[q][2] = fma2(rp, w2, acc[q][2]);
                acc[q][3] = fma2(rp, w3, acc[q][3]);
            }
        }
        #pragma unroll
        for (int q = 0; q < 4; q++)
            #pragma unroll
            for (int n = 0; n < 4; n++) {
                float2 v = up(acc[q][n]);
                vmax[2*q  ][n] = fmaxf(vmax[2*q  ][n], v.x);
                vmax[2*q+1][n] = fmaxf(vmax[2*q+1][n], v.y);
            }
        __syncthreads();
    }

    // x = tanh(max + b_m2) -> s_x transposed [col][row]
    {
        float4 bb = *reinterpret_cast<const float4*>(&b_m2[c4]);
        #pragma unroll
        for (int m = 0; m < 8; m++) {
            s_x[(c4  )*PM + rb + m] = tanha(vmax[m][0] + bb.x);
            s_x[(c4+1)*PM + rb + m] = tanha(vmax[m][1] + bb.y);
            s_x[(c4+2)*PM + rb + m] = tanha(vmax[m][2] + bb.z);
            s_x[(c4+3)*PM + rb + m] = tanha(vmax[m][3] + bb.w);
        }
    }
    __syncthreads();

    // y = tanh(x @ W_a1 + b_a1) -> s_m (reuse)
    {
        u64 acc[4][4];
        #pragma unroll
        for (int q = 0; q < 4; q++)
            #pragma unroll
            for (int n = 0; n < 4; n++) acc[q][n] = 0ull;
        #pragma unroll 4
        for (int kk = 0; kk < 128; kk++) {
            float4 w = *reinterpret_cast<const float4*>(&W_a1[kk*128 + c4]);
            u64 w0 = pk(w.x), w1 = pk(w.y), w2 = pk(w.z), w3 = pk(w.w);
            #pragma unroll
            for (int q = 0; q < 4; q++) {
                u64 xv = *reinterpret_cast<const u64*>(&s_x[kk*PM + rb + 2*q]);
                acc[q][0] = fma2(xv, w0, acc[q][0]);
                acc[q][1] = fma2(xv, w1, acc[q][1]);
                acc[q][2] = fma2(xv, w2, acc[q][2]);
                acc[q][3] = fma2(xv, w3, acc[q][3]);
            }
        }
        float4 bb = *reinterpret_cast<const float4*>(&b_a1[c4]);
        #pragma unroll
        for (int q = 0; q < 4; q++) {
            float2 a0 = up(acc[q][0]), a1 = up(acc[q][1]), a2 = up(acc[q][2]), a3 = up(acc[q][3]);
            s_m[(c4  )*PM + rb + 2*q]   = tanha(a0.x + bb.x);
            s_m[(c4  )*PM + rb + 2*q+1] = tanha(a0.y + bb.x);
            s_m[(c4+1)*PM + rb + 2*q]   = tanha(a1.x + bb.y);
            s_m[(c4+1)*PM + rb + 2*q+1] = tanha(a1.y + bb.y);
            s_m[(c4+2)*PM + rb + 2*q]   = tanha(a2.x + bb.z);
            s_m[(c4+2)*PM + rb + 2*q+1] = tanha(a2.y + bb.z);
            s_m[(c4+3)*PM + rb + 2*q]   = tanha(a3.x + bb.w);
            s_m[(c4+3)*PM + rb + 2*q+1] = tanha(a3.y + bb.w);
        }
    }
    __syncthreads();

    // final 128 -> 4, exact squashing
    {
        int r = tid >> 2, o = tid & 3;
        float s = b_a2[o];
        #pragma unroll 4
        for (int kk = 0; kk < 128; kk++) s += s_m[kk*PM + r] * W_a2[kk*4 + o];
        int row = row0 + r;
        int b = row / NB, n = row - b*NB;
        if (o < 2) {
            float tv = tar[row*2 + o];
            out[b*60 + 2*n + o] = 0.3f*tanhf(s) + 0.3f*tanhf(tv);
        } else {
            float t = tanhf(s);
            float ls = 3.5f*t - 1.5f;
            out[BSZ*60 + b*60 + 2*n + (o-2)] = expf(ls);
        }
    }
}

// ---------------- launch ----------------
extern "C" void kernel_launch(void* const* d_in, const int* in_sizes, int n_in,
                              void* d_out, int out_size)
{
    const float* state_inp = (const float*)d_in[0];
    const float* tar       = (const float*)d_in[1];
    const float* W_in1     = (const float*)d_in[2];
    const float* b_in1     = (const float*)d_in[3];
    const float* W_in2     = (const float*)d_in[4];
    const float* b_in2     = (const float*)d_in[5];
    const float* emb_tab   = (const float*)d_in[6];
    const float* W_emb     = (const float*)d_in[7];
    const float* b_emb     = (const float*)d_in[8];
    const float* W_m1      = (const float*)d_in[9];
    const float* b_m1      = (const float*)d_in[10];
    const float* W_m2      = (const float*)d_in[11];
    const float* b_m2      = (const float*)d_in[12];
    const float* W_a1      = (const float*)d_in[13];
    const float* b_a1      = (const float*)d_in[14];
    const float* W_a2      = (const float*)d_in[15];
    const float* b_a2      = (const float*)d_in[16];
    float* out = (float*)d_out;

    cudaFuncSetAttribute(k_msg, cudaFuncAttributeMaxDynamicSharedMemorySize, SMEM_MSG_BYTES);

    k_setup<<<64, 256>>>(emb_tab, W_emb, b_emb, W_m1);
    k_knn<<<BSZ, 32>>>(state_inp);
    k_feat<<<NROWS/32, 256>>>(state_inp, tar, W_in1, b_in1, W_in2, b_in2, b_m1);
    k_msg<<<NROWS/RMSG, 256, SMEM_MSG_BYTES>>>(tar, W_m2, b_m2, W_a1, b_a1, W_a2, b_a2, out);
}